// round 8
// baseline (speedup 1.0000x reference)
#include <cuda_runtime.h>
#include <math.h>
#include <cstdint>

#define FULL_MASK 0xFFFFFFFFu
typedef unsigned long long ull;

__device__ __forceinline__ ull pk2(float lo, float hi) {
    ull r; asm("mov.b64 %0, {%1, %2};" : "=l"(r) : "f"(lo), "f"(hi)); return r;
}
__device__ __forceinline__ void fma2(ull& d, ull a, ull b) {
    asm("fma.rn.f32x2 %0, %1, %2, %0;" : "+l"(d) : "l"(a), "l"(b));
}
__device__ __forceinline__ void unpk(ull v, float& a, float& b) {
    asm("mov.b64 {%0, %1}, %2;" : "=f"(a), "=f"(b) : "l"(v));
}

// bs=65536, S=10, D=100, H=16, 5 greedy steps.
// s-per-lane: warp handles a TRIPLE of batches; lane = (b3 = l/10, s = l%10),
// lanes 30/31 shadow 28/29. Each lane computes ALL 16 h of its row, so one corpus
// value feeds 8 f32x2 (16 MACs) from registers; weight pairs {Wp[d][2h],Wp[d][2h+1]}
// come free from row-major layout via uniform (broadcast) LDS.
//
// R8 = R7 with register pressure removed (R6/R7 spilled at the 128-reg cap ->
// local-memory traffic + latency collapse): t-loop ROLLED, c-loop unroll 2,
// staging without integer divides. Computation order is byte-identical to R7.
//
// FROZEN numerics contract (rel_err 9.309e-8 since R4):
//   - every dot: single-accumulator sequential-k fmaf chain (ascending), bias AFTER
//   - f32x2 pairs two INDEPENDENT h-chains (lo/hi rounded separately)
//   - src = mean(ui): append-order sum; /2,/4 exact mul; /3,/5 via __fdiv_rn
//   - softmax skipped (monotone); first-index argmax via strict >
__global__ __launch_bounds__(96, 5)
void attn_greedy_kernel(const float* __restrict__ g_ui,     // [bs,16]
                        const float* __restrict__ g_corp,   // [bs,10,100]
                        const float* __restrict__ g_wp,     // [100,16]
                        const float* __restrict__ g_bp,     // [16]
                        const float* __restrict__ g_wk,     // [16,16]
                        const float* __restrict__ g_bk,     // [16]
                        float* __restrict__ g_out,          // [bs,6,16]
                        int n_batch)
{
    __shared__ __align__(16) float s_corp[3][3000];      // per-warp corpus [b3*1000 + s*100 + d]
    __shared__ __align__(16) float s_wp[100 * 16];       // W_proj row-major [d][h]
    __shared__ __align__(16) float s_wk[16 * 16];        // W_k row-major [k][h]
    __shared__ __align__(16) float s_bp[16];
    __shared__ __align__(16) float s_bk[16];

    const int tid  = threadIdx.x;
    const int w    = tid >> 5;
    const int lane = tid & 31;
    const int l    = (lane < 30) ? lane : (lane - 2);    // lanes 30,31 shadow 28,29
    const int b3   = l / 10;
    const int s    = l - b3 * 10;
    const int grp  = b3 * 10;
    const bool writer = (lane < 30);

    // ---- stage weights once per block ----
    for (int i = tid; i < 1600; i += 96) s_wp[i] = g_wp[i];
    for (int i = tid; i < 256;  i += 96) s_wk[i] = g_wk[i];
    if (tid < 16) { s_bp[tid] = g_bp[tid]; s_bk[tid] = g_bk[tid]; }
    __syncthreads();

    const int warp_id  = blockIdx.x * 3 + w;
    const int n_warps  = gridDim.x * 3;
    const int n_triple = (n_batch + 2) / 3;
    float* scw = s_corp[w];

    for (int tr = warp_id; tr < n_triple; tr += n_warps) {
        const int  tb    = tr * 3;
        const int  b     = tb + b3;
        const bool valid = writer && (b < n_batch);
        const int  bl    = (b < n_batch) ? b : (n_batch - 1);

        // ---- stage triple corpus: coalesced LDG.128 -> STS.128, per-batch sub-loops ----
        #pragma unroll
        for (int j = 0; j < 3; j++) {
            int bj = tb + j; if (bj >= n_batch) bj = n_batch - 1;
            const float4* gsrc = (const float4*)(g_corp + (size_t)bj * 1000);
            float4* sdst = (float4*)(scw + j * 1000);
            #pragma unroll
            for (int i = 0; i < 8; i++) {
                int idx = lane + 32 * i;
                if (idx < 250) sdst[idx] = gsrc[idx];
            }
        }

        // ---- ui: every lane of a group holds the full 16-vector ----
        float sum[16];
        {
            const float4* u4 = (const float4*)(g_ui + (size_t)bl * 16);
            #pragma unroll
            for (int i = 0; i < 4; i++) {
                float4 v = u4[i];
                sum[4*i]=v.x; sum[4*i+1]=v.y; sum[4*i+2]=v.z; sum[4*i+3]=v.w;
            }
        }
        if (valid) {
            float* o = g_out + (size_t)b * 96;
            o[s] = sum[s];
            if (s < 6) o[10 + s] = sum[10 + s];
        }
        __syncwarp();                                    // staging visible

        // ---- projection: ic[h] = seq-fma_{d=0..99} corp[s,d]*Wp[d,h], then +bp ----
        ull icp[8];
        #pragma unroll
        for (int p = 0; p < 8; p++) icp[p] = 0ull;
        const float* crow = scw + b3 * 1000 + s * 100;
        #pragma unroll 2
        for (int c = 0; c < 25; c++) {
            float4 cv = *(const float4*)(crow + 4 * c);  // d = 4c..4c+3
            #pragma unroll
            for (int q = 0; q < 4; q++) {                // d ascending
                float cd = (q == 0) ? cv.x : (q == 1) ? cv.y : (q == 2) ? cv.z : cv.w;
                ull cdd = pk2(cd, cd);
                const ulonglong2* wr = (const ulonglong2*)(s_wp + (4*c + q) * 16);  // uniform LDS
                #pragma unroll
                for (int i = 0; i < 4; i++) {
                    ulonglong2 wp2 = wr[i];
                    fma2(icp[2*i],     cdd, wp2.x);
                    fma2(icp[2*i + 1], cdd, wp2.y);
                }
            }
        }
        float ic[16], src[16];
        {
            const float4* b4 = (const float4*)s_bp;
            #pragma unroll
            for (int i = 0; i < 4; i++) {
                float a0,a1,a2,a3; float4 bv = b4[i];
                unpk(icp[2*i], a0, a1); unpk(icp[2*i+1], a2, a3);
                ic[4*i]=a0+bv.x; ic[4*i+1]=a1+bv.y; ic[4*i+2]=a2+bv.z; ic[4*i+3]=a3+bv.w;
            }
        }
        #pragma unroll
        for (int h = 0; h < 16; h++) src[h] = sum[h];    // mean of 1 vector

        // ---- 5 greedy steps (t-loop ROLLED to keep registers below the cap) ----
        for (int t = 1; t <= 5; t++) {
            // nic[h] = seq-fma_{k=0..15} ic[k]*Wk[k][h], then +bk
            ull np[8];
            #pragma unroll
            for (int p = 0; p < 8; p++) np[p] = 0ull;
            #pragma unroll
            for (int k = 0; k < 16; k++) {               // k ascending
                ull a2 = pk2(ic[k], ic[k]);
                const ulonglong2* wr = (const ulonglong2*)(s_wk + k * 16);  // uniform LDS
                #pragma unroll
                for (int i = 0; i < 4; i++) {
                    ulonglong2 wk2 = wr[i];
                    fma2(np[2*i],     a2, wk2.x);
                    fma2(np[2*i + 1], a2, wk2.y);
                }
            }
            float nic[16];
            {
                const float4* b4 = (const float4*)s_bk;
                #pragma unroll
                for (int i = 0; i < 4; i++) {
                    float a0,a1,a2,a3; float4 bv = b4[i];
                    unpk(np[2*i], a0, a1); unpk(np[2*i+1], a2, a3);
                    nic[4*i]=a0+bv.x; nic[4*i+1]=a1+bv.y; nic[4*i+2]=a2+bv.z; nic[4*i+3]=a3+bv.w;
                }
            }

            // score = seq-fma_{h=0..15} nic[h]*src[h]  (in-lane, h ascending)
            float sc = 0.f;
            #pragma unroll
            for (int h = 0; h < 16; h++) sc = fmaf(nic[h], src[h], sc);

            // first-index argmax over the 10 lanes of this group (strict >)
            float bv = -INFINITY; int idx = 0;
            #pragma unroll
            for (int j = 0; j < 10; j++) {
                float v = __shfl_sync(FULL_MASK, sc, grp + j);
                if (v > bv) { bv = v; idx = j; }
            }

            // broadcast selected row; update sum; write output
            const int srcl = grp + idx;
            float* o = g_out + (size_t)b * 96 + (size_t)t * 16;
            #pragma unroll
            for (int h = 0; h < 16; h++) {
                float it = __shfl_sync(FULL_MASK, nic[h], srcl);
                sum[h] += it;                            // append-order running sum
                if (valid && (h == s || h == s + 10)) o[h] = it;
            }

            // next step's src = mean over t+1 vectors
            if (t == 1) {
                #pragma unroll
                for (int h = 0; h < 16; h++) src[h] = sum[h] * 0.5f;
            } else if (t == 3) {
                #pragma unroll
                for (int h = 0; h < 16; h++) src[h] = sum[h] * 0.25f;
            } else if (t < 5) {
                const float dv = (float)(t + 1);
                #pragma unroll
                for (int h = 0; h < 16; h++) src[h] = __fdiv_rn(sum[h], dv);
            }

            #pragma unroll
            for (int h = 0; h < 16; h++) ic[h] = nic[h];
        }
        __syncwarp();                                    // corpus reads done before restage
    }
}

extern "C" void kernel_launch(void* const* d_in, const int* in_sizes, int n_in,
                              void* d_out, int out_size) {
    const float* ui     = (const float*)d_in[0];
    const float* corpus = (const float*)d_in[1];
    const float* wp     = (const float*)d_in[2];
    const float* bp     = (const float*)d_in[3];
    const float* wk     = (const float*)d_in[4];
    const float* bk     = (const float*)d_in[5];
    float* out = (float*)d_out;
    int n_batch = in_sizes[0] / 16;
    // 96-thread blocks, 43.3KB smem -> 5 blocks/SM (15 warps). 740 = 5 x 148 SMs.
    attn_greedy_kernel<<<740, 96>>>(ui, corpus, wp, bp, wk, bk, out, n_batch);
}

// round 9
// speedup vs baseline: 3.0256x; 3.0256x over previous
#include <cuda_runtime.h>
#include <math.h>
#include <cstdint>

#define FULL_MASK 0xFFFFFFFFu
typedef unsigned long long ull;

__device__ __forceinline__ ull pk2(float lo, float hi) {
    ull r; asm("mov.b64 %0, {%1, %2};" : "=l"(r) : "f"(lo), "f"(hi)); return r;
}
__device__ __forceinline__ void fma2(ull& d, ull a, ull b) {
    asm("fma.rn.f32x2 %0, %1, %2, %0;" : "+l"(d) : "l"(a), "l"(b));
}
__device__ __forceinline__ void unpk(ull v, float& a, float& b) {
    asm("mov.b64 {%0, %1}, %2;" : "=f"(a), "=f"(b) : "l"(v));
}

// bs=65536, S=10, D=100, H=16, 5 greedy steps.
// 4 batches per warp; lane = (b4 = lane>>3, g = (lane>>2)&1, hq = lane&3).
// Lane owns a 5-row x 4-col tile: rows 5g..5g+4, cols h0..h0+3 (h0 = 4*hq).
// Corpus streamed per-lane via __ldcs (each value delivered once per (g-group) — 4x less
// crossbar redundancy than R5); weights via __ldg (sector-dedup'd, L1-resident);
// ic lives in smem row-major only; matmul k-reads are scalar BROADCAST LDS (1 wf).
//
// FROZEN numerics contract (rel_err 9.309e-8 since R4):
//   - every dot: single-accumulator sequential fmaf chain (ascending index), bias AFTER
//   - f32x2 pairs two INDEPENDENT h-chains (lo/hi rounded separately)
//   - score: ONE lane per (batch,row), h=0..15 ascending scalar chain
//   - src = mean(ui): append-order sum; /2,/4 exact mul; /3,/5 via __fdiv_rn
//   - softmax skipped (monotone); first-index argmax via strict >
__global__ __launch_bounds__(128, 4)
void attn_greedy_kernel(const float* __restrict__ g_ui,     // [bs,16]
                        const float* __restrict__ g_corp,   // [bs,10,100]
                        const float* __restrict__ g_wp,     // [100,16]
                        const float* __restrict__ g_bp,     // [16]
                        const float* __restrict__ g_wk,     // [16,16]
                        const float* __restrict__ g_bk,     // [16]
                        float* __restrict__ g_out,          // [bs,6,16]
                        int n_batch)
{
    __shared__ __align__(16) float s_ic[4][4][10][20];   // [warp][b4][row][h(pad 20)]
    __shared__ __align__(16) float s_src[4][4][16];      // [warp][b4][h]
    __shared__ float s_score[4][4][10];                  // [warp][b4][row]

    const int tid  = threadIdx.x;
    const int w    = tid >> 5;
    const int lane = tid & 31;
    const int b4   = lane >> 3;
    const int g    = (lane >> 2) & 1;
    const int hq   = lane & 3;
    const int h0   = hq << 2;

    const int warp_id = (blockIdx.x << 2) + w;
    const int n_warps = gridDim.x << 2;
    const int n_quad  = (n_batch + 3) >> 2;

    const float4 bp4 = __ldg((const float4*)(g_bp + h0));
    const float4 bk4 = __ldg((const float4*)(g_bk + h0));

    for (int qd = warp_id; qd < n_quad; qd += n_warps) {
        const int  b     = (qd << 2) + b4;
        const bool valid = (b < n_batch);
        const int  bl    = valid ? b : (n_batch - 1);

        // ---- ui: lane holds its 4-h slice; g0 lanes own sum/src and t0 output ----
        float4 uiv = __ldg((const float4*)(g_ui + (size_t)bl * 16 + h0));
        float sum0 = uiv.x, sum1 = uiv.y, sum2 = uiv.z, sum3 = uiv.w;
        if (g == 0) {
            *(float4*)&s_src[w][b4][h0] = uiv;
            if (valid) *(float4*)(g_out + (size_t)b * 96 + h0) = uiv;
        }

        // ---- projection: ic0[row][h] = seq-fma_{d=0..99} corp[row,d]*Wp[d,h], +bp ----
        ull acc[5][2];
        #pragma unroll
        for (int j = 0; j < 5; j++) { acc[j][0] = 0ull; acc[j][1] = 0ull; }
        const float* crow = g_corp + (size_t)bl * 1000 + (5 * g) * 100;
        #pragma unroll 5
        for (int c = 0; c < 25; c++) {
            float4 x[5];
            #pragma unroll
            for (int j = 0; j < 5; j++)
                x[j] = __ldcs((const float4*)(crow + j * 100 + 4 * c));   // streaming
            #pragma unroll
            for (int q = 0; q < 4; q++) {                                 // d ascending
                ulonglong2 wp2 = __ldg((const ulonglong2*)(g_wp + (4*c + q) * 16 + h0));
                #pragma unroll
                for (int j = 0; j < 5; j++) {
                    float cd = (q == 0) ? x[j].x : (q == 1) ? x[j].y : (q == 2) ? x[j].z : x[j].w;
                    ull cdd = pk2(cd, cd);
                    fma2(acc[j][0], cdd, wp2.x);    // chains h0, h0+1
                    fma2(acc[j][1], cdd, wp2.y);    // chains h0+2, h0+3
                }
            }
        }
        #pragma unroll
        for (int j = 0; j < 5; j++) {
            float a0, a1, a2, a3;
            unpk(acc[j][0], a0, a1); unpk(acc[j][1], a2, a3);
            *(float4*)&s_ic[w][b4][5*g + j][h0] =
                make_float4(a0 + bp4.x, a1 + bp4.y, a2 + bp4.z, a3 + bp4.w);
        }
        __syncwarp();

        // ---- 5 greedy steps ----
        for (int t = 1; t <= 5; t++) {
            // nic[row][h] = seq-fma_{k=0..15} ic[row][k]*Wk[k][h], +bk
            ull np[5][2];
            #pragma unroll
            for (int j = 0; j < 5; j++) { np[j][0] = 0ull; np[j][1] = 0ull; }
            #pragma unroll
            for (int k = 0; k < 16; k++) {                                // k ascending
                ulonglong2 wk2 = __ldg((const ulonglong2*)(g_wk + k * 16 + h0));
                #pragma unroll
                for (int j = 0; j < 5; j++) {
                    float iv = s_ic[w][b4][5*g + j][k];                   // scalar broadcast LDS
                    ull iv2 = pk2(iv, iv);
                    fma2(np[j][0], iv2, wk2.x);
                    fma2(np[j][1], iv2, wk2.y);
                }
            }
            float nic[5][4];
            #pragma unroll
            for (int j = 0; j < 5; j++) {
                float a0, a1, a2, a3;
                unpk(np[j][0], a0, a1); unpk(np[j][1], a2, a3);
                nic[j][0] = a0 + bk4.x; nic[j][1] = a1 + bk4.y;
                nic[j][2] = a2 + bk4.z; nic[j][3] = a3 + bk4.w;
            }
            __syncwarp();                       // all k-reads of old ic done
            #pragma unroll
            for (int j = 0; j < 5; j++)
                *(float4*)&s_ic[w][b4][5*g + j][h0] =
                    make_float4(nic[j][0], nic[j][1], nic[j][2], nic[j][3]);
            __syncwarp();                       // new ic visible

            // score[(sb,row)] = seq-fma_{h=0..15} ic[row][h]*src[h]  (one lane per row)
            {
                const int sb = lane >> 3, sr = lane & 7;
                const float* icr = s_ic[w][sb][sr];
                const float* sv  = s_src[w][sb];
                float a = 0.f;
                #pragma unroll
                for (int i = 0; i < 4; i++) {
                    float4 xx = *(const float4*)(icr + 4*i);
                    float4 yy = *(const float4*)(sv + 4*i);
                    a = fmaf(xx.x, yy.x, a); a = fmaf(xx.y, yy.y, a);     // h ascending
                    a = fmaf(xx.z, yy.z, a); a = fmaf(xx.w, yy.w, a);
                }
                s_score[w][sb][sr] = a;
                if (sr < 2) {                    // rows 8,9
                    const float* icr2 = s_ic[w][sb][8 + sr];
                    float a2 = 0.f;
                    #pragma unroll
                    for (int i = 0; i < 4; i++) {
                        float4 xx = *(const float4*)(icr2 + 4*i);
                        float4 yy = *(const float4*)(sv + 4*i);
                        a2 = fmaf(xx.x, yy.x, a2); a2 = fmaf(xx.y, yy.y, a2);
                        a2 = fmaf(xx.z, yy.z, a2); a2 = fmaf(xx.w, yy.w, a2);
                    }
                    s_score[w][sb][8 + sr] = a2;
                }
            }
            __syncwarp();

            // first-index argmax (strict >, ascending row)
            float bv = -INFINITY; int idx = 0;
            #pragma unroll
            for (int j = 0; j < 10; j++) {
                float v = s_score[w][b4][j];     // broadcast LDS
                if (v > bv) { bv = v; idx = j; }
            }

            // gather selected row via register select + shfl
            const int jj = idx - 5 * g;          // 0..4 if this g owns the row
            float c0 = nic[0][0], c1 = nic[0][1], c2 = nic[0][2], c3 = nic[0][3];
            #pragma unroll
            for (int j = 1; j < 5; j++)
                if (jj == j) { c0 = nic[j][0]; c1 = nic[j][1]; c2 = nic[j][2]; c3 = nic[j][3]; }
            const int srcl = (lane & 24) | ((idx >= 5) ? 4 : 0) | hq;
            float it0 = __shfl_sync(FULL_MASK, c0, srcl);
            float it1 = __shfl_sync(FULL_MASK, c1, srcl);
            float it2 = __shfl_sync(FULL_MASK, c2, srcl);
            float it3 = __shfl_sync(FULL_MASK, c3, srcl);

            sum0 += it0; sum1 += it1; sum2 += it2; sum3 += it3;          // append order
            if (g == 0) {
                if (valid)
                    *(float4*)(g_out + (size_t)b * 96 + (size_t)t * 16 + h0) =
                        make_float4(it0, it1, it2, it3);
                if (t < 5) {
                    float s0, s1, s2, s3;
                    if (t == 1)      { s0 = sum0*0.5f;  s1 = sum1*0.5f;  s2 = sum2*0.5f;  s3 = sum3*0.5f;  }
                    else if (t == 3) { s0 = sum0*0.25f; s1 = sum1*0.25f; s2 = sum2*0.25f; s3 = sum3*0.25f; }
                    else {
                        const float dv = (float)(t + 1);
                        s0 = __fdiv_rn(sum0, dv); s1 = __fdiv_rn(sum1, dv);
                        s2 = __fdiv_rn(sum2, dv); s3 = __fdiv_rn(sum3, dv);
                    }
                    *(float4*)&s_src[w][b4][h0] = make_float4(s0, s1, s2, s3);
                }
            }
        }
        __syncwarp();                            // s_ic/s_src reads done before next quad
    }
}

extern "C" void kernel_launch(void* const* d_in, const int* in_sizes, int n_in,
                              void* d_out, int out_size) {
    const float* ui     = (const float*)d_in[0];
    const float* corpus = (const float*)d_in[1];
    const float* wp     = (const float*)d_in[2];
    const float* bp     = (const float*)d_in[3];
    const float* wk     = (const float*)d_in[4];
    const float* bk     = (const float*)d_in[5];
    float* out = (float*)d_out;
    int n_batch = in_sizes[0] / 16;
    // 128-thread blocks, ~15KB smem, reg cap 128 (4 blocks/SM = 16 warps). 592 = 4 x 148.
    attn_greedy_kernel<<<592, 128>>>(ui, corpus, wp, bp, wk, bk, out, n_batch);
}